// round 16
// baseline (speedup 1.0000x reference)
#include <cuda_runtime.h>
#include <cuda_bf16.h>
#include <cstdint>
#include <math.h>

#define BATCH   16384
#define FK      64
#define VISD    2048
#define HID     512
#define NUSERS  1000000
#define VOCAB   (NUSERS + 24 + 2 + 8 + 40)

// Scratch (allocation-free rule: __device__ globals)
__device__ __nv_bfloat16 g_xh [BATCH * 384];
__device__ __nv_bfloat16 g_h1h[BATCH * HID];
__device__ __nv_bfloat16 g_w1h[HID * 384];
__device__ __nv_bfloat16 g_w2h[HID * HID];
__device__ __nv_bfloat16 g_wvh[FK * VISD];     // visu_w bf16
__device__ float         g_fm [BATCH * 2];
__device__ float2        g_part[BATCH * 8];

// ---------------------------------------------------------------------------
// helpers (portable PTX only — harness targets compute_103, no 'a' features)
// ---------------------------------------------------------------------------
__device__ __forceinline__ uint32_t smem_u32(const void* p) {
    uint32_t a;
    asm("{ .reg .u64 t; cvta.to.shared.u64 t, %1; cvt.u32.u64 %0, t; }"
        : "=r"(a) : "l"(p));
    return a;
}
__device__ __forceinline__ void cp16(uint32_t s, const void* g) {
    asm volatile("cp.async.cg.shared.global [%0], [%1], 16;" :: "r"(s), "l"(g));
}
__device__ __forceinline__ void cp_commit() {
    asm volatile("cp.async.commit_group;" ::: "memory");
}
template<int N> __device__ __forceinline__ void cp_wait() {
    asm volatile("cp.async.wait_group %0;" :: "n"(N) : "memory");
}
__device__ __forceinline__ void ldsm4(uint32_t r[4], uint32_t addr) {
    asm volatile("ldmatrix.sync.aligned.m8n8.x4.shared.b16 {%0,%1,%2,%3}, [%4];"
        : "=r"(r[0]), "=r"(r[1]), "=r"(r[2]), "=r"(r[3]) : "r"(addr));
}
__device__ __forceinline__ void mma_bf16(float d[4], const uint32_t a[4],
                                         const uint32_t b[2]) {
    asm volatile(
        "mma.sync.aligned.m16n8k16.row.col.f32.bf16.bf16.f32 "
        "{%0,%1,%2,%3}, {%4,%5,%6,%7}, {%8,%9}, {%0,%1,%2,%3};"
        : "+f"(d[0]), "+f"(d[1]), "+f"(d[2]), "+f"(d[3])
        : "r"(a[0]), "r"(a[1]), "r"(a[2]), "r"(a[3]), "r"(b[0]), "r"(b[1]));
}
__device__ __forceinline__ uint32_t pack_bf16(float lo, float hi) {
    uint32_t r;
    asm("cvt.rn.bf16x2.f32 %0, %1, %2;" : "=r"(r) : "f"(hi), "f"(lo));
    return r;
}

// ---------------------------------------------------------------------------
// Weight conversions
// ---------------------------------------------------------------------------
__global__ void conv_w_kernel(const float* __restrict__ w1,
                              const float* __restrict__ w2)
{
    const int N1 = HID * 384 / 4;
    int i = blockIdx.x * blockDim.x + threadIdx.x;
    if (i < N1) {
        float4 v = ((const float4*)w1)[i];
        uint2 o = { pack_bf16(v.x, v.y), pack_bf16(v.z, v.w) };
        ((uint2*)g_w1h)[i] = o;
    } else {
        int j = i - N1;
        float4 v = ((const float4*)w2)[j];
        uint2 o = { pack_bf16(v.x, v.y), pack_bf16(v.z, v.w) };
        ((uint2*)g_w2h)[j] = o;
    }
}

__global__ void conv_visuw_kernel(const float* __restrict__ vw)
{
    int i = blockIdx.x * blockDim.x + threadIdx.x;   // 32768 float4
    float4 v = ((const float4*)vw)[i];
    uint2 o = { pack_bf16(v.x, v.y), pack_bf16(v.z, v.w) };
    ((uint2*)g_wvh)[i] = o;
}

// ---------------------------------------------------------------------------
// vis GEMM bf16, BK=64 (proven R15). A fp32 via cp.async (3 stages),
// converted smem->smem into double-buffered bf16 tile. One barrier/iter.
// ---------------------------------------------------------------------------
__global__ __launch_bounds__(256, 2) void gemm_vis_bf16(
    const float* __restrict__ A,
    const __nv_bfloat16* __restrict__ W,
    const float* __restrict__ bias,
    __nv_bfloat16* __restrict__ C)
{
    constexpr int BM = 64, BN = 64, BK = 64, S = 3;
    constexpr int LDF = 68;
    constexpr int LDW = 36;
    constexpr int AFSZ = BM * LDF;
    constexpr int WSZ  = BN * LDW;
    constexpr int AHSZ = BM * LDW;

    extern __shared__ uint32_t smw[];
    uint32_t* sAF = smw;
    uint32_t* sW  = smw + S * AFSZ;
    uint32_t* sAH = smw + S * AFSZ + S * WSZ;
    __shared__ float sbias[BN];

    const int tid = threadIdx.x;
    const int m0  = blockIdx.x * BM;
    const int NC  = VISD / BK;

    if (tid < BN) sbias[tid] = bias[tid];

    const uint32_t sAFu = smem_u32(sAF);
    const uint32_t sWu  = smem_u32(sW);
    const uint32_t sAHu = smem_u32(sAH);

    auto loadA = [&](int c) {
        const int st = c % S;
        const int k0 = c * BK;
        #pragma unroll
        for (int j = 0; j < 4; j++) {
            int idx = tid + j * 256;
            int r = idx >> 4, f4 = idx & 15;
            cp16(sAFu + (st * AFSZ + r * LDF + f4 * 4) * 4,
                 A + (size_t)(m0 + r) * VISD + k0 + f4 * 4);
        }
    };
    auto convA = [&](int c) {
        const int st = c % S;
        const int b  = c & 1;
        #pragma unroll
        for (int j = 0; j < 4; j++) {
            int idx = tid + j * 256;
            int r = idx >> 4, f4 = idx & 15;
            float4 v = *(const float4*)(sAF + st * AFSZ + r * LDF + f4 * 4);
            uint2 o = { pack_bf16(v.x, v.y), pack_bf16(v.z, v.w) };
            *(uint2*)(sAH + b * AHSZ + r * LDW + f4 * 2) = o;
        }
    };
    auto loadW = [&](int c) {
        const int st = c % S;
        const int k0 = c * BK;
        #pragma unroll
        for (int j = 0; j < 2; j++) {
            int idx = tid + j * 256;
            int r = idx >> 3, sg = idx & 7;
            cp16(sWu + (st * WSZ + r * LDW + sg * 4) * 4,
                 W + (size_t)r * VISD + k0 + sg * 8);
        }
    };

    const int lane = tid & 31, warp = tid >> 5;
    const int g = lane >> 2, t = lane & 3;
    const int wm = warp & 1, wn = warp >> 1;
    const int mbase = wm * 32, nbase = wn * 16;
    const uint32_t rowA  = ((lane >> 3) & 1) * 8 + (lane & 7);
    const uint32_t abyte = (lane >> 4) * 16;
    const uint32_t rowB  = ((lane >> 4) << 3) + (lane & 7);
    const uint32_t bbyte = ((lane >> 3) & 1) * 16;

    float acc[2][2][4] = {};

    loadA(0); loadW(0); cp_commit();
    loadA(1); loadW(1); cp_commit();
    cp_wait<1>();
    convA(0);
    __syncthreads();

    for (int c = 0; c < NC; c++) {
        if (c > 0) __syncthreads();
        if (c + 2 < NC) { loadA(c + 2); loadW(c + 2); }
        cp_commit();
        cp_wait<1>();
        if (c + 1 < NC) convA(c + 1);

        const uint32_t stA = sAHu + (c & 1) * AHSZ * 4;
        const uint32_t stW = sWu + (c % S) * WSZ * 4;
        #pragma unroll
        for (int ks = 0; ks < 4; ks++) {
            uint32_t af[2][4], bf4[4];
            #pragma unroll
            for (int tm = 0; tm < 2; tm++)
                ldsm4(af[tm], stA + (mbase + tm * 16 + rowA) * (LDW * 4)
                              + ks * 32 + abyte);
            ldsm4(bf4, stW + (nbase + rowB) * (LDW * 4) + ks * 32 + bbyte);
            #pragma unroll
            for (int tm = 0; tm < 2; tm++) {
                mma_bf16(acc[tm][0], af[tm], bf4 + 0);
                mma_bf16(acc[tm][1], af[tm], bf4 + 2);
            }
        }
    }

    #pragma unroll
    for (int tm = 0; tm < 2; tm++) {
        #pragma unroll
        for (int tn = 0; tn < 2; tn++) {
            const int ncol = nbase + tn * 8 + 2 * t;
            const float b0 = sbias[ncol], b1 = sbias[ncol + 1];
            #pragma unroll
            for (int half = 0; half < 2; half++) {
                const int row = m0 + mbase + tm * 16 + g + half * 8;
                float vx = acc[tm][tn][half * 2 + 0] + b0;
                float vy = acc[tm][tn][half * 2 + 1] + b1;
                *(uint32_t*)(C + (size_t)row * 384 + 320 + ncol) =
                    pack_bf16(vx, vy);
            }
        }
    }
}

// ---------------------------------------------------------------------------
// MLP bf16 GEMM pieces: BK=64, S=2, LDW=36, one barrier per iteration.
// 256 threads, 8 warps (4m x 2n), warp tile 32x64.
// ---------------------------------------------------------------------------
#define MLP_DECL                                                              \
    constexpr int BK = 64, S = 2, LDW = 36;                                   \
    constexpr int WM = 4, WN = 2, TN = 8;                                     \
    constexpr int BM = 128, BN = 128;                                         \
    constexpr int ASZ = BM * LDW;                                             \
    constexpr int WSZ = BN * LDW;                                             \
    (void)0

#define MLP_LOADER(Aptr, lda, Wptr, ldw)                                      \
    auto load_tiles = [&](int c) {                                            \
        const int st = c % S;                                                 \
        const int k0 = c * BK;                                                \
        _Pragma("unroll")                                                     \
        for (int j = 0; j < 4; j++) {                                         \
            int i = tid + j * 256;                                            \
            int r = i >> 3, sg = i & 7;                                       \
            cp16(sAu + (st * ASZ + r * LDW + sg * 4) * 4,                     \
                 Aptr + (size_t)(m0 + r) * lda + k0 + sg * 8);                \
        }                                                                     \
        _Pragma("unroll")                                                     \
        for (int j = 0; j < 4; j++) {                                         \
            int i = tid + j * 256;                                            \
            int r = i >> 3, sg = i & 7;                                       \
            cp16(sWu + (st * WSZ + r * LDW + sg * 4) * 4,                     \
                 Wptr + (size_t)(n0 + r) * ldw + k0 + sg * 8);                \
        }                                                                     \
    }

#define MLP_COMMON_IDX                                                        \
    const int lane = tid & 31, warp = tid >> 5;                               \
    const int g = lane >> 2, t = lane & 3;                                    \
    const int wm = warp % WM, wn = warp / WM;                                 \
    const int mbase = wm * 32;                                                \
    const int nbase = wn * (BN / WN);                                         \
    const uint32_t rowA  = ((lane >> 3) & 1) * 8 + (lane & 7);                \
    const uint32_t abyte = (lane >> 4) * 16;                                  \
    const uint32_t rowB  = ((lane >> 4) << 3) + (lane & 7);                   \
    const uint32_t bbyte = ((lane >> 3) & 1) * 16

#define MLP_MAINLOOP(NC)                                                      \
    load_tiles(0); cp_commit();                                               \
    for (int c = 0; c < (NC); c++) {                                          \
        __syncthreads();                                                      \
        if (c + 1 < (NC)) load_tiles(c + 1);                                  \
        cp_commit();                                                          \
        cp_wait<1>();                                                         \
        __syncthreads();                                                      \
        const uint32_t stA = sAu + (c % S) * ASZ * 4;                         \
        const uint32_t stW = sWu + (c % S) * WSZ * 4;                         \
        _Pragma("unroll")                                                     \
        for (int ks = 0; ks < 4; ks++) {                                      \
            uint32_t af[2][4], bf[4][4];                                      \
            _Pragma("unroll")                                                 \
            for (int tm = 0; tm < 2; tm++)                                    \
                ldsm4(af[tm], stA + (mbase + tm * 16 + rowA) * (LDW * 4)      \
                              + ks * 32 + abyte);                             \
            _Pragma("unroll")                                                 \
            for (int p = 0; p < 4; p++)                                       \
                ldsm4(bf[p], stW + (nbase + p * 16 + rowB) * (LDW * 4)        \
                              + ks * 32 + bbyte);                             \
            _Pragma("unroll")                                                 \
            for (int tm = 0; tm < 2; tm++)                                    \
                _Pragma("unroll")                                             \
                for (int p = 0; p < 4; p++) {                                 \
                    mma_bf16(acc[tm][2 * p],     af[tm], bf[p] + 0);          \
                    mma_bf16(acc[tm][2 * p + 1], af[tm], bf[p] + 2);          \
                }                                                             \
        }                                                                     \
    }

// ---------------------------------------------------------------------------
// mlp1: h1 = relu(x @ w1^T + b1) -> bf16   (K=384, 6 iterations)
// ---------------------------------------------------------------------------
__global__ __launch_bounds__(256, 2) void gemm_mlp1(
    const __nv_bfloat16* __restrict__ A,
    const __nv_bfloat16* __restrict__ W,
    const float* __restrict__ bias,
    __nv_bfloat16* __restrict__ C)
{
    MLP_DECL;
    extern __shared__ uint32_t smw[];
    uint32_t* sA = smw;
    uint32_t* sW = smw + S * ASZ;
    __shared__ float sbias[BN];

    const int tid = threadIdx.x;
    const int m0  = blockIdx.y * BM;
    const int n0  = blockIdx.x * BN;

    if (tid < BN) sbias[tid] = bias[n0 + tid];

    const uint32_t sAu = smem_u32(sA);
    const uint32_t sWu = smem_u32(sW);
    MLP_LOADER(A, 384, W, 384);
    MLP_COMMON_IDX;

    float acc[2][TN][4] = {};
    MLP_MAINLOOP(384 / BK);

    #pragma unroll
    for (int tm = 0; tm < 2; tm++) {
        #pragma unroll
        for (int tn = 0; tn < TN; tn++) {
            const int ncol = nbase + tn * 8 + 2 * t;
            const float b0 = sbias[ncol], b1 = sbias[ncol + 1];
            const int gcol = n0 + ncol;
            #pragma unroll
            for (int half = 0; half < 2; half++) {
                const int row = m0 + mbase + tm * 16 + g + half * 8;
                float vx = fmaxf(acc[tm][tn][half * 2 + 0] + b0, 0.f);
                float vy = fmaxf(acc[tm][tn][half * 2 + 1] + b1, 0.f);
                *(uint32_t*)(C + (size_t)row * HID + gcol) = pack_bf16(vx, vy);
            }
        }
    }
}

// ---------------------------------------------------------------------------
// mlp2 + fused logits: h2 in regs only -> per-block logit partials (K=512)
// ---------------------------------------------------------------------------
__global__ __launch_bounds__(256, 2) void gemm_mlp2_last(
    const __nv_bfloat16* __restrict__ A,
    const __nv_bfloat16* __restrict__ W,
    const float* __restrict__ bias,
    const float* __restrict__ w3)
{
    MLP_DECL;
    extern __shared__ uint32_t smw[];
    uint32_t* sA = smw;
    uint32_t* sW = smw + S * ASZ;
    __shared__ float sbias[BN];
    __shared__ float w3s[2][BN];

    const int tid = threadIdx.x;
    const int m0  = blockIdx.y * BM;
    const int n0  = blockIdx.x * BN;

    if (tid < BN) {
        sbias[tid]  = bias[n0 + tid];
        w3s[0][tid] = w3[n0 + tid];
        w3s[1][tid] = w3[HID + n0 + tid];
    }

    const uint32_t sAu = smem_u32(sA);
    const uint32_t sWu = smem_u32(sW);
    MLP_LOADER(A, HID, W, HID);
    MLP_COMMON_IDX;

    float acc[2][TN][4] = {};
    MLP_MAINLOOP(HID / BK);

    const int pidx = blockIdx.x * 2 + wn;
    #pragma unroll
    for (int tm = 0; tm < 2; tm++) {
        #pragma unroll
        for (int half = 0; half < 2; half++) {
            const int row = m0 + mbase + tm * 16 + g + half * 8;
            float s0 = 0.f, s1 = 0.f;
            #pragma unroll
            for (int tn = 0; tn < TN; tn++) {
                const int ncol = nbase + tn * 8 + 2 * t;
                float v0 = fmaxf(acc[tm][tn][half * 2 + 0] + sbias[ncol],     0.f);
                float v1 = fmaxf(acc[tm][tn][half * 2 + 1] + sbias[ncol + 1], 0.f);
                s0 = fmaf(v0, w3s[0][ncol], fmaf(v1, w3s[0][ncol + 1], s0));
                s1 = fmaf(v0, w3s[1][ncol], fmaf(v1, w3s[1][ncol + 1], s1));
            }
            s0 += __shfl_xor_sync(0xffffffffu, s0, 1);
            s0 += __shfl_xor_sync(0xffffffffu, s0, 2);
            s1 += __shfl_xor_sync(0xffffffffu, s1, 1);
            s1 += __shfl_xor_sync(0xffffffffu, s1, 2);
            if (t == 0)
                g_part[row * 8 + pidx] = make_float2(s0, s1);
        }
    }
}

// ---------------------------------------------------------------------------
// Embeddings + FM (1st + 2nd order) -> g_xh[:, 0:320], g_fm
// ---------------------------------------------------------------------------
__global__ void embed_fm_kernel(
    const int* __restrict__ uid, const int* __restrict__ hour,
    const float* __restrict__ scale,
    const int* __restrict__ gender, const int* __restrict__ age,
    const int* __restrict__ attr,
    const float* __restrict__ user_emb, const float* __restrict__ hour_emb,
    const float* __restrict__ gender_emb, const float* __restrict__ age_emb,
    const float* __restrict__ attr_emb,
    const float* __restrict__ fm_w, const float* __restrict__ fm_b)
{
    int s = threadIdx.x >> 6;
    int k = threadIdx.x & 63;
    int b = blockIdx.x * 4 + s;

    int u  = uid[b];
    int h  = hour[b];
    int g  = gender[b];
    int a  = age[b];
    int at = attr[b];
    float sc = scale[b];

    float e0 = user_emb[(size_t)u * 64 + k];
    float e1 = hour_emb[h * 64 + k];
    float e2 = sc * tanhf(gender_emb[g * 64 + k]);
    float e3 = sc * tanhf(attr_emb[at * 64 + k]);
    float e4 = sc * tanhf(age_emb[a * 64 + k]);

    __nv_bfloat16* xb = g_xh + (size_t)b * 384;
    xb[      k] = __float2bfloat16_rn(e0);
    xb[ 64 + k] = __float2bfloat16_rn(e1);
    xb[128 + k] = __float2bfloat16_rn(e2);
    xb[192 + k] = __float2bfloat16_rn(e3);
    xb[256 + k] = __float2bfloat16_rn(e4);

    float su = e0 + e1 + e2 + e3 + e4;
    float sq = e0*e0 + e1*e1 + e2*e2 + e3*e3 + e4*e4;
    float so = su * su - sq;

    #pragma unroll
    for (int o = 16; o > 0; o >>= 1)
        so += __shfl_down_sync(0xffffffffu, so, o);

    __shared__ float red[4][2];
    if ((k & 31) == 0) red[s][k >> 5] = so;
    __syncthreads();

    if (k == 0) {
        float second = 0.5f * (red[s][0] + red[s][1]);
        long c0 = u;
        long c1 = NUSERS + h;
        long c2 = NUSERS + 24 + g;
        long c3 = NUSERS + 26 + a;
        long c4 = NUSERS + 34 + at;
        #pragma unroll
        for (int j = 0; j < 2; j++) {
            const float* w = fm_w + (size_t)j * VOCAB;
            g_fm[b * 2 + j] =
                w[c0] + w[c1] + w[c2] + w[c3] + w[c4] + fm_b[j] + second;
        }
    }
}

// ---------------------------------------------------------------------------
// Softmax over (fm + b3 + sum of 8 partials), fixed summation order.
// ---------------------------------------------------------------------------
__global__ void softmax_kernel(const float* __restrict__ b3,
                               float* __restrict__ out)
{
    int b = blockIdx.x * 256 + threadIdx.x;
    float s0 = 0.f, s1 = 0.f;
    #pragma unroll
    for (int p = 0; p < 8; p++) {
        float2 v = g_part[b * 8 + p];
        s0 += v.x; s1 += v.y;
    }
    float l0 = g_fm[b * 2 + 0] + b3[0] + s0;
    float l1 = g_fm[b * 2 + 1] + b3[1] + s1;
    float m  = fmaxf(l0, l1);
    float e0 = expf(l0 - m), e1 = expf(l1 - m);
    float inv = 1.0f / (e0 + e1);
    out[b * 2 + 0] = e0 * inv;
    out[b * 2 + 1] = e1 * inv;
}

// ---------------------------------------------------------------------------
extern "C" void kernel_launch(void* const* d_in, const int* in_sizes, int n_in,
                              void* d_out, int out_size)
{
    const int*   uid        = (const int*)  d_in[0];
    const int*   hour       = (const int*)  d_in[1];
    const float* visual     = (const float*)d_in[2];
    const float* scale      = (const float*)d_in[3];
    const int*   gender     = (const int*)  d_in[4];
    const int*   age        = (const int*)  d_in[5];
    const int*   attribute  = (const int*)  d_in[6];
    const float* user_emb   = (const float*)d_in[7];
    const float* hour_emb   = (const float*)d_in[8];
    const float* gender_emb = (const float*)d_in[9];
    const float* age_emb    = (const float*)d_in[10];
    const float* attr_emb   = (const float*)d_in[11];
    const float* visu_w     = (const float*)d_in[12];
    const float* visu_b     = (const float*)d_in[13];
    const float* fm_w       = (const float*)d_in[14];
    const float* fm_b       = (const float*)d_in[15];
    const float* w1         = (const float*)d_in[16];
    const float* b1         = (const float*)d_in[17];
    const float* w2         = (const float*)d_in[18];
    const float* b2         = (const float*)d_in[19];
    const float* w3         = (const float*)d_in[20];
    const float* b3         = (const float*)d_in[21];
    float* out = (float*)d_out;

    __nv_bfloat16 *xhp, *h1p, *w1p, *w2p, *wvp;
    cudaGetSymbolAddress((void**)&xhp, g_xh);
    cudaGetSymbolAddress((void**)&h1p, g_h1h);
    cudaGetSymbolAddress((void**)&w1p, g_w1h);
    cudaGetSymbolAddress((void**)&w2p, g_w2h);
    cudaGetSymbolAddress((void**)&wvp, g_wvh);

    const int SM_VIS = (3 * 64 * 68 + 3 * 64 * 36 + 2 * 64 * 36) * 4; // 98,304
    const int SM_MLP = 2 * (128 + 128) * 36 * 4;                      // 73,728
    cudaFuncSetAttribute(gemm_vis_bf16,  cudaFuncAttributeMaxDynamicSharedMemorySize, SM_VIS);
    cudaFuncSetAttribute(gemm_mlp1,      cudaFuncAttributeMaxDynamicSharedMemorySize, SM_MLP);
    cudaFuncSetAttribute(gemm_mlp2_last, cudaFuncAttributeMaxDynamicSharedMemorySize, SM_MLP);

    cudaStream_t s1, s2;
    cudaStreamCreateWithFlags(&s1, cudaStreamNonBlocking);
    cudaStreamCreateWithFlags(&s2, cudaStreamNonBlocking);
    cudaEvent_t ev0, ev1, ev2;
    cudaEventCreateWithFlags(&ev0, cudaEventDisableTiming);
    cudaEventCreateWithFlags(&ev1, cudaEventDisableTiming);
    cudaEventCreateWithFlags(&ev2, cudaEventDisableTiming);

    cudaEventRecord(ev0, 0);
    cudaStreamWaitEvent(s1, ev0, 0);
    cudaStreamWaitEvent(s2, ev0, 0);

    // branch 1 (s1): convert visu_w (~2 us), then bf16 vis GEMM
    conv_visuw_kernel<<<FK * VISD / 4 / 256, 256, 0, s1>>>(visu_w);
    gemm_vis_bf16<<<BATCH / 64, 256, SM_VIS, s1>>>(visual, wvp, visu_b, xhp);

    // branch 2 (s2): convert w1, w2
    conv_w_kernel<<<448, 256, 0, s2>>>(w1, w2);

    // main: embeddings + FM
    embed_fm_kernel<<<BATCH / 4, 256>>>(uid, hour, scale, gender, age, attribute,
                                        user_emb, hour_emb, gender_emb, age_emb,
                                        attr_emb, fm_w, fm_b);

    cudaEventRecord(ev1, s1);
    cudaEventRecord(ev2, s2);
    cudaStreamWaitEvent(0, ev1, 0);
    cudaStreamWaitEvent(0, ev2, 0);

    // h1 = relu(x @ w1^T + b1)
    gemm_mlp1<<<dim3(HID / 128, BATCH / 128), 256, SM_MLP>>>(xhp, w1p, b1, h1p);

    // h2 (registers only) -> logit partials
    gemm_mlp2_last<<<dim3(HID / 128, BATCH / 128), 256, SM_MLP>>>(h1p, w2p, b2, w3);

    // softmax(fm + b3 + sum partials)
    softmax_kernel<<<BATCH / 256, 256>>>(b3, out);

    cudaEventDestroy(ev0);
    cudaEventDestroy(ev1);
    cudaEventDestroy(ev2);
    cudaStreamDestroy(s1);
    cudaStreamDestroy(s2);
}

// round 17
// speedup vs baseline: 1.0389x; 1.0389x over previous
#include <cuda_runtime.h>
#include <cuda_bf16.h>
#include <cstdint>
#include <math.h>

#define BATCH   16384
#define FK      64
#define VISD    2048
#define HID     512
#define NUSERS  1000000
#define VOCAB   (NUSERS + 24 + 2 + 8 + 40)

// Scratch (allocation-free rule: __device__ globals)
__device__ __nv_bfloat16 g_xh [BATCH * 384];
__device__ __nv_bfloat16 g_h1h[BATCH * HID];
__device__ __nv_bfloat16 g_w1h[HID * 384];
__device__ __nv_bfloat16 g_w2h[HID * HID];
__device__ __nv_bfloat16 g_wvh[FK * VISD];     // visu_w bf16
__device__ float         g_fm [BATCH * 2];
__device__ float2        g_part[BATCH * 8];

// ---------------------------------------------------------------------------
// helpers (portable PTX only — harness targets compute_103, no 'a' features)
// ---------------------------------------------------------------------------
__device__ __forceinline__ uint32_t smem_u32(const void* p) {
    uint32_t a;
    asm("{ .reg .u64 t; cvta.to.shared.u64 t, %1; cvt.u32.u64 %0, t; }"
        : "=r"(a) : "l"(p));
    return a;
}
__device__ __forceinline__ void cp16(uint32_t s, const void* g) {
    asm volatile("cp.async.cg.shared.global [%0], [%1], 16;" :: "r"(s), "l"(g));
}
__device__ __forceinline__ void cp_commit() {
    asm volatile("cp.async.commit_group;" ::: "memory");
}
template<int N> __device__ __forceinline__ void cp_wait() {
    asm volatile("cp.async.wait_group %0;" :: "n"(N) : "memory");
}
__device__ __forceinline__ void ldsm4(uint32_t r[4], uint32_t addr) {
    asm volatile("ldmatrix.sync.aligned.m8n8.x4.shared.b16 {%0,%1,%2,%3}, [%4];"
        : "=r"(r[0]), "=r"(r[1]), "=r"(r[2]), "=r"(r[3]) : "r"(addr));
}
__device__ __forceinline__ void mma_bf16(float d[4], const uint32_t a[4],
                                         const uint32_t b[2]) {
    asm volatile(
        "mma.sync.aligned.m16n8k16.row.col.f32.bf16.bf16.f32 "
        "{%0,%1,%2,%3}, {%4,%5,%6,%7}, {%8,%9}, {%0,%1,%2,%3};"
        : "+f"(d[0]), "+f"(d[1]), "+f"(d[2]), "+f"(d[3])
        : "r"(a[0]), "r"(a[1]), "r"(a[2]), "r"(a[3]), "r"(b[0]), "r"(b[1]));
}
__device__ __forceinline__ uint32_t pack_bf16(float lo, float hi) {
    uint32_t r;
    asm("cvt.rn.bf16x2.f32 %0, %1, %2;" : "=r"(r) : "f"(hi), "f"(lo));
    return r;
}

// ---------------------------------------------------------------------------
// Weight conversions
// ---------------------------------------------------------------------------
__global__ void conv_w_kernel(const float* __restrict__ w1,
                              const float* __restrict__ w2)
{
    const int N1 = HID * 384 / 4;
    int i = blockIdx.x * blockDim.x + threadIdx.x;
    if (i < N1) {
        float4 v = ((const float4*)w1)[i];
        uint2 o = { pack_bf16(v.x, v.y), pack_bf16(v.z, v.w) };
        ((uint2*)g_w1h)[i] = o;
    } else {
        int j = i - N1;
        float4 v = ((const float4*)w2)[j];
        uint2 o = { pack_bf16(v.x, v.y), pack_bf16(v.z, v.w) };
        ((uint2*)g_w2h)[j] = o;
    }
}

__global__ void conv_visuw_kernel(const float* __restrict__ vw)
{
    int i = blockIdx.x * blockDim.x + threadIdx.x;   // 32768 float4
    float4 v = ((const float4*)vw)[i];
    uint2 o = { pack_bf16(v.x, v.y), pack_bf16(v.z, v.w) };
    ((uint2*)g_wvh)[i] = o;
}

// ---------------------------------------------------------------------------
// vis GEMM bf16, BK=64. A fp32 via cp.async with S=4 staging (2 chunks of
// DRAM lookahead via cp_wait<2>), converted smem->smem into double-buffered
// bf16 tile. W bf16 via cp.async (S=3, prefetch c+2). One barrier/iter.
// ---------------------------------------------------------------------------
__global__ __launch_bounds__(256, 2) void gemm_vis_bf16(
    const float* __restrict__ A,
    const __nv_bfloat16* __restrict__ W,
    const float* __restrict__ bias,
    __nv_bfloat16* __restrict__ C)
{
    constexpr int BM = 64, BN = 64, BK = 64;
    constexpr int SA = 4, SW = 3;
    constexpr int LDF = 64;                  // fp32 staging row (no pad needed)
    constexpr int LDW = 36;                  // bf16 tile row (ldmatrix pad)
    constexpr int AFSZ = BM * LDF;           // 4096 words
    constexpr int WSZ  = BN * LDW;           // 2304 words
    constexpr int AHSZ = BM * LDW;           // 2304 words

    extern __shared__ uint32_t smw[];
    uint32_t* sAF = smw;                     // [SA][AFSZ]
    uint32_t* sW  = smw + SA * AFSZ;         // [SW][WSZ]
    uint32_t* sAH = smw + SA * AFSZ + SW * WSZ; // [2][AHSZ]
    __shared__ float sbias[BN];

    const int tid = threadIdx.x;
    const int m0  = blockIdx.x * BM;
    const int NC  = VISD / BK;               // 32

    if (tid < BN) sbias[tid] = bias[tid];

    const uint32_t sAFu = smem_u32(sAF);
    const uint32_t sWu  = smem_u32(sW);
    const uint32_t sAHu = smem_u32(sAH);

    auto loadA = [&](int c) {
        const int st = c % SA;
        const int k0 = c * BK;
        #pragma unroll
        for (int j = 0; j < 4; j++) {
            int idx = tid + j * 256;
            int r = idx >> 4, f4 = idx & 15;
            cp16(sAFu + (st * AFSZ + r * LDF + f4 * 4) * 4,
                 A + (size_t)(m0 + r) * VISD + k0 + f4 * 4);
        }
    };
    auto convA = [&](int c) {
        const int st = c % SA;
        const int b  = c & 1;
        #pragma unroll
        for (int j = 0; j < 4; j++) {
            int idx = tid + j * 256;
            int r = idx >> 4, f4 = idx & 15;
            float4 v = *(const float4*)(sAF + st * AFSZ + r * LDF + f4 * 4);
            uint2 o = { pack_bf16(v.x, v.y), pack_bf16(v.z, v.w) };
            *(uint2*)(sAH + b * AHSZ + r * LDW + f4 * 2) = o;
        }
    };
    auto loadW = [&](int c) {
        const int st = c % SW;
        const int k0 = c * BK;
        #pragma unroll
        for (int j = 0; j < 2; j++) {
            int idx = tid + j * 256;
            int r = idx >> 3, sg = idx & 7;
            cp16(sWu + (st * WSZ + r * LDW + sg * 4) * 4,
                 W + (size_t)r * VISD + k0 + sg * 8);
        }
    };

    const int lane = tid & 31, warp = tid >> 5;
    const int g = lane >> 2, t = lane & 3;
    const int wm = warp & 1, wn = warp >> 1;
    const int mbase = wm * 32, nbase = wn * 16;
    const uint32_t rowA  = ((lane >> 3) & 1) * 8 + (lane & 7);
    const uint32_t abyte = (lane >> 4) * 16;
    const uint32_t rowB  = ((lane >> 4) << 3) + (lane & 7);
    const uint32_t bbyte = ((lane >> 3) & 1) * 16;

    float acc[2][2][4] = {};

    // prologue: G0={A0,W0}, G1={A1,W1}, G2={A2}
    loadA(0); loadW(0); cp_commit();
    loadA(1); loadW(1); cp_commit();
    loadA(2);           cp_commit();
    cp_wait<2>();                            // G0 done: A0, W0
    convA(0);
    __syncthreads();

    for (int c = 0; c < NC; c++) {
        if (c > 0) __syncthreads();          // retire iter c-1 reads
        if (c + 3 < NC) loadA(c + 3);
        if (c + 2 < NC) loadW(c + 2);
        cp_commit();                         // G(3+c)
        cp_wait<2>();                        // A(c+1), W(c) resident
        if (c + 1 < NC) convA(c + 1);

        const uint32_t stA = sAHu + (c & 1) * AHSZ * 4;
        const uint32_t stW = sWu + (c % SW) * WSZ * 4;
        #pragma unroll
        for (int ks = 0; ks < 4; ks++) {
            uint32_t af[2][4], bf4[4];
            #pragma unroll
            for (int tm = 0; tm < 2; tm++)
                ldsm4(af[tm], stA + (mbase + tm * 16 + rowA) * (LDW * 4)
                              + ks * 32 + abyte);
            ldsm4(bf4, stW + (nbase + rowB) * (LDW * 4) + ks * 32 + bbyte);
            #pragma unroll
            for (int tm = 0; tm < 2; tm++) {
                mma_bf16(acc[tm][0], af[tm], bf4 + 0);
                mma_bf16(acc[tm][1], af[tm], bf4 + 2);
            }
        }
    }

    #pragma unroll
    for (int tm = 0; tm < 2; tm++) {
        #pragma unroll
        for (int tn = 0; tn < 2; tn++) {
            const int ncol = nbase + tn * 8 + 2 * t;
            const float b0 = sbias[ncol], b1 = sbias[ncol + 1];
            #pragma unroll
            for (int half = 0; half < 2; half++) {
                const int row = m0 + mbase + tm * 16 + g + half * 8;
                float vx = acc[tm][tn][half * 2 + 0] + b0;
                float vy = acc[tm][tn][half * 2 + 1] + b1;
                *(uint32_t*)(C + (size_t)row * 384 + 320 + ncol) =
                    pack_bf16(vx, vy);
            }
        }
    }
}

// ---------------------------------------------------------------------------
// MLP bf16 GEMM pieces (proven R15: BK=32, S=3, LDW=20; 8 warps 4x2, 32x64)
// ---------------------------------------------------------------------------
#define MLP_DECL                                                              \
    constexpr int BK = 32, S = 3, LDW = 20;                                   \
    constexpr int WM = 4, WN = 2, TN = 8;                                     \
    constexpr int BM = 128, BN = 128;                                         \
    constexpr int ASZ = BM * LDW;                                             \
    constexpr int WSZ = BN * LDW;                                             \
    (void)0

#define MLP_LOADER(Aptr, lda, Wptr, ldw)                                      \
    auto load_tiles = [&](int c) {                                            \
        const int st = c % S;                                                 \
        const int k0 = c * BK;                                                \
        _Pragma("unroll")                                                     \
        for (int j = 0; j < 2; j++) {                                         \
            int i = tid + j * 256;                                            \
            int r = i >> 2, sg = i & 3;                                       \
            cp16(sAu + (st * ASZ + r * LDW + sg * 4) * 4,                     \
                 Aptr + (size_t)(m0 + r) * lda + k0 + sg * 8);                \
        }                                                                     \
        _Pragma("unroll")                                                     \
        for (int j = 0; j < 2; j++) {                                         \
            int i = tid + j * 256;                                            \
            int r = i >> 2, sg = i & 3;                                       \
            cp16(sWu + (st * WSZ + r * LDW + sg * 4) * 4,                     \
                 Wptr + (size_t)(n0 + r) * ldw + k0 + sg * 8);                \
        }                                                                     \
    }

#define MLP_COMMON_IDX                                                        \
    const int lane = tid & 31, warp = tid >> 5;                               \
    const int g = lane >> 2, t = lane & 3;                                    \
    const int wm = warp % WM, wn = warp / WM;                                 \
    const int mbase = wm * 32;                                                \
    const int nbase = wn * (BN / WN);                                         \
    const uint32_t rowA  = ((lane >> 3) & 1) * 8 + (lane & 7);                \
    const uint32_t abyte = (lane >> 4) * 16;                                  \
    const uint32_t rowB  = ((lane >> 4) << 3) + (lane & 7);                   \
    const uint32_t bbyte = ((lane >> 3) & 1) * 16

#define MLP_MAINLOOP(NC)                                                      \
    load_tiles(0); cp_commit();                                               \
    load_tiles(1); cp_commit();                                               \
    for (int c = 0; c < (NC); c++) {                                          \
        cp_wait<1>();                                                         \
        __syncthreads();                                                      \
        if (c + 2 < (NC)) load_tiles(c + 2);                                  \
        cp_commit();                                                          \
        const uint32_t stA = sAu + (c % S) * ASZ * 4;                         \
        const uint32_t stW = sWu + (c % S) * WSZ * 4;                         \
        _Pragma("unroll")                                                     \
        for (int ks = 0; ks < 2; ks++) {                                      \
            uint32_t af[2][4], bf[4][4];                                      \
            _Pragma("unroll")                                                 \
            for (int tm = 0; tm < 2; tm++)                                    \
                ldsm4(af[tm], stA + (mbase + tm * 16 + rowA) * (LDW * 4)      \
                              + ks * 32 + abyte);                             \
            _Pragma("unroll")                                                 \
            for (int p = 0; p < 4; p++)                                       \
                ldsm4(bf[p], stW + (nbase + p * 16 + rowB) * (LDW * 4)        \
                              + ks * 32 + bbyte);                             \
            _Pragma("unroll")                                                 \
            for (int tm = 0; tm < 2; tm++)                                    \
                _Pragma("unroll")                                             \
                for (int p = 0; p < 4; p++) {                                 \
                    mma_bf16(acc[tm][2 * p],     af[tm], bf[p] + 0);          \
                    mma_bf16(acc[tm][2 * p + 1], af[tm], bf[p] + 2);          \
                }                                                             \
        }                                                                     \
    }

// ---------------------------------------------------------------------------
// mlp1: h1 = relu(x @ w1^T + b1) -> bf16
// ---------------------------------------------------------------------------
__global__ __launch_bounds__(256, 2) void gemm_mlp1(
    const __nv_bfloat16* __restrict__ A,
    const __nv_bfloat16* __restrict__ W,
    const float* __restrict__ bias,
    __nv_bfloat16* __restrict__ C)
{
    MLP_DECL;
    extern __shared__ uint32_t smw[];
    uint32_t* sA = smw;
    uint32_t* sW = smw + S * ASZ;
    __shared__ float sbias[BN];

    const int tid = threadIdx.x;
    const int m0  = blockIdx.y * BM;
    const int n0  = blockIdx.x * BN;

    if (tid < BN) sbias[tid] = bias[n0 + tid];

    const uint32_t sAu = smem_u32(sA);
    const uint32_t sWu = smem_u32(sW);
    MLP_LOADER(A, 384, W, 384);
    MLP_COMMON_IDX;

    float acc[2][TN][4] = {};
    MLP_MAINLOOP(384 / BK);

    #pragma unroll
    for (int tm = 0; tm < 2; tm++) {
        #pragma unroll
        for (int tn = 0; tn < TN; tn++) {
            const int ncol = nbase + tn * 8 + 2 * t;
            const float b0 = sbias[ncol], b1 = sbias[ncol + 1];
            const int gcol = n0 + ncol;
            #pragma unroll
            for (int half = 0; half < 2; half++) {
                const int row = m0 + mbase + tm * 16 + g + half * 8;
                float vx = fmaxf(acc[tm][tn][half * 2 + 0] + b0, 0.f);
                float vy = fmaxf(acc[tm][tn][half * 2 + 1] + b1, 0.f);
                *(uint32_t*)(C + (size_t)row * HID + gcol) = pack_bf16(vx, vy);
            }
        }
    }
}

// ---------------------------------------------------------------------------
// mlp2 + fused logits: h2 in regs only -> per-block logit partials
// ---------------------------------------------------------------------------
__global__ __launch_bounds__(256, 2) void gemm_mlp2_last(
    const __nv_bfloat16* __restrict__ A,
    const __nv_bfloat16* __restrict__ W,
    const float* __restrict__ bias,
    const float* __restrict__ w3)
{
    MLP_DECL;
    extern __shared__ uint32_t smw[];
    uint32_t* sA = smw;
    uint32_t* sW = smw + S * ASZ;
    __shared__ float sbias[BN];
    __shared__ float w3s[2][BN];

    const int tid = threadIdx.x;
    const int m0  = blockIdx.y * BM;
    const int n0  = blockIdx.x * BN;

    if (tid < BN) {
        sbias[tid]  = bias[n0 + tid];
        w3s[0][tid] = w3[n0 + tid];
        w3s[1][tid] = w3[HID + n0 + tid];
    }

    const uint32_t sAu = smem_u32(sA);
    const uint32_t sWu = smem_u32(sW);
    MLP_LOADER(A, HID, W, HID);
    MLP_COMMON_IDX;

    float acc[2][TN][4] = {};
    MLP_MAINLOOP(HID / BK);

    const int pidx = blockIdx.x * 2 + wn;
    #pragma unroll
    for (int tm = 0; tm < 2; tm++) {
        #pragma unroll
        for (int half = 0; half < 2; half++) {
            const int row = m0 + mbase + tm * 16 + g + half * 8;
            float s0 = 0.f, s1 = 0.f;
            #pragma unroll
            for (int tn = 0; tn < TN; tn++) {
                const int ncol = nbase + tn * 8 + 2 * t;
                float v0 = fmaxf(acc[tm][tn][half * 2 + 0] + sbias[ncol],     0.f);
                float v1 = fmaxf(acc[tm][tn][half * 2 + 1] + sbias[ncol + 1], 0.f);
                s0 = fmaf(v0, w3s[0][ncol], fmaf(v1, w3s[0][ncol + 1], s0));
                s1 = fmaf(v0, w3s[1][ncol], fmaf(v1, w3s[1][ncol + 1], s1));
            }
            s0 += __shfl_xor_sync(0xffffffffu, s0, 1);
            s0 += __shfl_xor_sync(0xffffffffu, s0, 2);
            s1 += __shfl_xor_sync(0xffffffffu, s1, 1);
            s1 += __shfl_xor_sync(0xffffffffu, s1, 2);
            if (t == 0)
                g_part[row * 8 + pidx] = make_float2(s0, s1);
        }
    }
}

// ---------------------------------------------------------------------------
// Embeddings + FM (1st + 2nd order) -> g_xh[:, 0:320], g_fm
// ---------------------------------------------------------------------------
__global__ void embed_fm_kernel(
    const int* __restrict__ uid, const int* __restrict__ hour,
    const float* __restrict__ scale,
    const int* __restrict__ gender, const int* __restrict__ age,
    const int* __restrict__ attr,
    const float* __restrict__ user_emb, const float* __restrict__ hour_emb,
    const float* __restrict__ gender_emb, const float* __restrict__ age_emb,
    const float* __restrict__ attr_emb,
    const float* __restrict__ fm_w, const float* __restrict__ fm_b)
{
    int s = threadIdx.x >> 6;
    int k = threadIdx.x & 63;
    int b = blockIdx.x * 4 + s;

    int u  = uid[b];
    int h  = hour[b];
    int g  = gender[b];
    int a  = age[b];
    int at = attr[b];
    float sc = scale[b];

    float e0 = user_emb[(size_t)u * 64 + k];
    float e1 = hour_emb[h * 64 + k];
    float e2 = sc * tanhf(gender_emb[g * 64 + k]);
    float e3 = sc * tanhf(attr_emb[at * 64 + k]);
    float e4 = sc * tanhf(age_emb[a * 64 + k]);

    __nv_bfloat16* xb = g_xh + (size_t)b * 384;
    xb[      k] = __float2bfloat16_rn(e0);
    xb[ 64 + k] = __float2bfloat16_rn(e1);
    xb[128 + k] = __float2bfloat16_rn(e2);
    xb[192 + k] = __float2bfloat16_rn(e3);
    xb[256 + k] = __float2bfloat16_rn(e4);

    float su = e0 + e1 + e2 + e3 + e4;
    float sq = e0*e0 + e1*e1 + e2*e2 + e3*e3 + e4*e4;
    float so = su * su - sq;

    #pragma unroll
    for (int o = 16; o > 0; o >>= 1)
        so += __shfl_down_sync(0xffffffffu, so, o);

    __shared__ float red[4][2];
    if ((k & 31) == 0) red[s][k >> 5] = so;
    __syncthreads();

    if (k == 0) {
        float second = 0.5f * (red[s][0] + red[s][1]);
        long c0 = u;
        long c1 = NUSERS + h;
        long c2 = NUSERS + 24 + g;
        long c3 = NUSERS + 26 + a;
        long c4 = NUSERS + 34 + at;
        #pragma unroll
        for (int j = 0; j < 2; j++) {
            const float* w = fm_w + (size_t)j * VOCAB;
            g_fm[b * 2 + j] =
                w[c0] + w[c1] + w[c2] + w[c3] + w[c4] + fm_b[j] + second;
        }
    }
}

// ---------------------------------------------------------------------------
// Softmax over (fm + b3 + sum of 8 partials), fixed summation order.
// ---------------------------------------------------------------------------
__global__ void softmax_kernel(const float* __restrict__ b3,
                               float* __restrict__ out)
{
    int b = blockIdx.x * 256 + threadIdx.x;
    float s0 = 0.f, s1 = 0.f;
    #pragma unroll
    for (int p = 0; p < 8; p++) {
        float2 v = g_part[b * 8 + p];
        s0 += v.x; s1 += v.y;
    }
    float l0 = g_fm[b * 2 + 0] + b3[0] + s0;
    float l1 = g_fm[b * 2 + 1] + b3[1] + s1;
    float m  = fmaxf(l0, l1);
    float e0 = expf(l0 - m), e1 = expf(l1 - m);
    float inv = 1.0f / (e0 + e1);
    out[b * 2 + 0] = e0 * inv;
    out[b * 2 + 1] = e1 * inv;
}

// ---------------------------------------------------------------------------
extern "C" void kernel_launch(void* const* d_in, const int* in_sizes, int n_in,
                              void* d_out, int out_size)
{
    const int*   uid        = (const int*)  d_in[0];
    const int*   hour       = (const int*)  d_in[1];
    const float* visual     = (const float*)d_in[2];
    const float* scale      = (const float*)d_in[3];
    const int*   gender     = (const int*)  d_in[4];
    const int*   age        = (const int*)  d_in[5];
    const int*   attribute  = (const int*)  d_in[6];
    const float* user_emb   = (const float*)d_in[7];
    const float* hour_emb   = (const float*)d_in[8];
    const float* gender_emb = (const float*)d_in[9];
    const float* age_emb    = (const float*)d_in[10];
    const float* attr_emb   = (const float*)d_in[11];
    const float* visu_w     = (const float*)d_in[12];
    const float* visu_b     = (const float*)d_in[13];
    const float* fm_w       = (const float*)d_in[14];
    const float* fm_b       = (const float*)d_in[15];
    const float* w1         = (const float*)d_in[16];
    const float* b1         = (const float*)d_in[17];
    const float* w2         = (const float*)d_in[18];
    const float* b2         = (const float*)d_in[19];
    const float* w3         = (const float*)d_in[20];
    const float* b3         = (const float*)d_in[21];
    float* out = (float*)d_out;

    __nv_bfloat16 *xhp, *h1p, *w1p, *w2p, *wvp;
    cudaGetSymbolAddress((void**)&xhp, g_xh);
    cudaGetSymbolAddress((void**)&h1p, g_h1h);
    cudaGetSymbolAddress((void**)&w1p, g_w1h);
    cudaGetSymbolAddress((void**)&w2p, g_w2h);
    cudaGetSymbolAddress((void**)&wvp, g_wvh);

    // vis: 4 fp32 A stages (64x64) + 3 W stages (64x36) + 2 bf16 A bufs (64x36)
    const int SM_VIS = (4 * 64 * 64 + 3 * 64 * 36 + 2 * 64 * 36) * 4; // 111,616
    const int SM_MLP = 3 * (128 + 128) * 20 * 4;                      // 61,440
    cudaFuncSetAttribute(gemm_vis_bf16,  cudaFuncAttributeMaxDynamicSharedMemorySize, SM_VIS);
    cudaFuncSetAttribute(gemm_mlp1,      cudaFuncAttributeMaxDynamicSharedMemorySize, SM_MLP);
    cudaFuncSetAttribute(gemm_mlp2_last, cudaFuncAttributeMaxDynamicSharedMemorySize, SM_MLP);

    cudaStream_t s1, s2;
    cudaStreamCreateWithFlags(&s1, cudaStreamNonBlocking);
    cudaStreamCreateWithFlags(&s2, cudaStreamNonBlocking);
    cudaEvent_t ev0, ev1, ev2;
    cudaEventCreateWithFlags(&ev0, cudaEventDisableTiming);
    cudaEventCreateWithFlags(&ev1, cudaEventDisableTiming);
    cudaEventCreateWithFlags(&ev2, cudaEventDisableTiming);

    cudaEventRecord(ev0, 0);
    cudaStreamWaitEvent(s1, ev0, 0);
    cudaStreamWaitEvent(s2, ev0, 0);

    // branch 1 (s1): convert visu_w (~2 us), then bf16 vis GEMM
    conv_visuw_kernel<<<FK * VISD / 4 / 256, 256, 0, s1>>>(visu_w);
    gemm_vis_bf16<<<BATCH / 64, 256, SM_VIS, s1>>>(visual, wvp, visu_b, xhp);

    // branch 2 (s2): convert w1, w2
    conv_w_kernel<<<448, 256, 0, s2>>>(w1, w2);

    // main: embeddings + FM
    embed_fm_kernel<<<BATCH / 4, 256>>>(uid, hour, scale, gender, age, attribute,
                                        user_emb, hour_emb, gender_emb, age_emb,
                                        attr_emb, fm_w, fm_b);

    cudaEventRecord(ev1, s1);
    cudaEventRecord(ev2, s2);
    cudaStreamWaitEvent(0, ev1, 0);
    cudaStreamWaitEvent(0, ev2, 0);

    // h1 = relu(x @ w1^T + b1)
    gemm_mlp1<<<dim3(HID / 128, BATCH / 128), 256, SM_MLP>>>(xhp, w1p, b1, h1p);

    // h2 (registers only) -> logit partials
    gemm_mlp2_last<<<dim3(HID / 128, BATCH / 128), 256, SM_MLP>>>(h1p, w2p, b2, w3);

    // softmax(fm + b3 + sum partials)
    softmax_kernel<<<BATCH / 256, 256>>>(b3, out);

    cudaEventDestroy(ev0);
    cudaEventDestroy(ev1);
    cudaEventDestroy(ev2);
    cudaStreamDestroy(s1);
    cudaStreamDestroy(s2);
}